// round 1
// baseline (speedup 1.0000x reference)
#include <cuda_runtime.h>
#include <cstdint>

// Problem constants
#define BATCH 8
#define HH 64
#define WW 64
#define CIN 256
#define DMID 64       // reduction dim
#define EOUT 144      // K*K*G = 9*16
#define PTOT (BATCH*HH*WW)   // 32768

// Scratch (device globals: allocation-free)
__device__ float g_t[PTOT * DMID];     // 8.4 MB
__device__ float g_wgt[PTOT * EOUT];   // 18.9 MB

// ---------------------------------------------------------------------------
// GEMM1: t[P,64] = x[P,256] @ W1[256,64] + b1
// BM=128, BN=64, BK=32; 256 threads; thread tile 8(M)x4(N)
// ---------------------------------------------------------------------------
__global__ __launch_bounds__(256) void gemm1_kernel(
    const float* __restrict__ x, const float* __restrict__ W1,
    const float* __restrict__ b1)
{
    __shared__ float As[32][129];   // [k][m], padded stride for conflict-free
    __shared__ float Bs[32][64];    // [k][n]
    const int block_m = blockIdx.x * 128;
    const int tid = threadIdx.x;
    const int tm = tid >> 4;        // 0..15 -> 8 rows each
    const int tn = tid & 15;        // 0..15 -> 4 cols each

    float acc[8][4];
    #pragma unroll
    for (int i = 0; i < 8; i++)
        #pragma unroll
        for (int j = 0; j < 4; j++) acc[i][j] = 0.f;

    for (int k0 = 0; k0 < CIN; k0 += 32) {
        // load x tile 128x32 (transposed into As[k][m])
        #pragma unroll
        for (int p = 0; p < 4; p++) {
            int r  = (tid >> 3) + p * 32;   // row in tile
            int c4 = (tid & 7);             // float4 col
            float4 v = *(const float4*)(x + (size_t)(block_m + r) * CIN + k0 + c4 * 4);
            As[c4*4+0][r] = v.x;
            As[c4*4+1][r] = v.y;
            As[c4*4+2][r] = v.z;
            As[c4*4+3][r] = v.w;
        }
        // load W1 tile 32x64
        #pragma unroll
        for (int p = 0; p < 8; p++) {
            int id = tid + p * 256;
            int kk = id >> 6, nn = id & 63;
            Bs[kk][nn] = W1[(size_t)(k0 + kk) * DMID + nn];
        }
        __syncthreads();

        #pragma unroll
        for (int k = 0; k < 32; k++) {
            float a[8], b[4];
            #pragma unroll
            for (int i = 0; i < 8; i++) a[i] = As[k][tm * 8 + i];
            float4 bv = *(const float4*)(&Bs[k][tn * 4]);
            b[0] = bv.x; b[1] = bv.y; b[2] = bv.z; b[3] = bv.w;
            #pragma unroll
            for (int i = 0; i < 8; i++)
                #pragma unroll
                for (int j = 0; j < 4; j++)
                    acc[i][j] += a[i] * b[j];
        }
        __syncthreads();
    }

    float bb0 = b1[tn*4+0], bb1 = b1[tn*4+1], bb2 = b1[tn*4+2], bb3 = b1[tn*4+3];
    #pragma unroll
    for (int i = 0; i < 8; i++) {
        int row = block_m + tm * 8 + i;
        float4 v = make_float4(acc[i][0] + bb0, acc[i][1] + bb1,
                               acc[i][2] + bb2, acc[i][3] + bb3);
        *(float4*)(g_t + (size_t)row * DMID + tn * 4) = v;
    }
}

// ---------------------------------------------------------------------------
// GEMM2: wgt[P,144] = t[P,64] @ W2[64,144] + b2
// BM=64, full N=144, full K=64 in smem; 256 threads; thread tile 4(M)x9(N)
// dynamic smem: Ts[64][65] + Ws[64][144]  = 53504 bytes
// ---------------------------------------------------------------------------
__global__ __launch_bounds__(256) void gemm2_kernel(
    const float* __restrict__ W2, const float* __restrict__ b2)
{
    extern __shared__ float sm2[];
    float* Ts = sm2;                 // [64][65] transposed: Ts[d][m]
    float* Ws = sm2 + 64 * 65;       // [64][144]
    const int block_m = blockIdx.x * 64;
    const int tid = threadIdx.x;

    // load t tile 64x64 (transposed)
    #pragma unroll
    for (int p = 0; p < 4; p++) {
        int id = tid + p * 256;      // float4 id, 1024 total
        int r  = id >> 4;            // row 0..63
        int c4 = id & 15;
        float4 v = *(const float4*)(g_t + (size_t)(block_m + r) * DMID + c4 * 4);
        Ts[(c4*4+0)*65 + r] = v.x;
        Ts[(c4*4+1)*65 + r] = v.y;
        Ts[(c4*4+2)*65 + r] = v.z;
        Ts[(c4*4+3)*65 + r] = v.w;
    }
    // load whole W2 (64*144 floats)
    for (int id = tid; id < 64 * EOUT; id += 256) Ws[id] = W2[id];
    __syncthreads();

    const int tm = tid >> 4;   // 0..15, 4 rows each
    const int tn = tid & 15;   // 0..15, 9 cols each
    float acc[4][9];
    #pragma unroll
    for (int i = 0; i < 4; i++)
        #pragma unroll
        for (int j = 0; j < 9; j++) acc[i][j] = 0.f;

    #pragma unroll 4
    for (int d = 0; d < 64; d++) {
        float a[4], b[9];
        #pragma unroll
        for (int i = 0; i < 4; i++) a[i] = Ts[d * 65 + tm * 4 + i];
        #pragma unroll
        for (int j = 0; j < 9; j++) b[j] = Ws[d * EOUT + tn * 9 + j];
        #pragma unroll
        for (int i = 0; i < 4; i++)
            #pragma unroll
            for (int j = 0; j < 9; j++)
                acc[i][j] += a[i] * b[j];
    }

    #pragma unroll
    for (int i = 0; i < 4; i++) {
        int row = block_m + tm * 4 + i;
        float* dst = g_wgt + (size_t)row * EOUT + tn * 9;
        #pragma unroll
        for (int j = 0; j < 9; j++) dst[j] = acc[i][j] + b2[tn * 9 + j];
    }
}

// ---------------------------------------------------------------------------
// Involution: out[b,y,x,oc] = sum_k2 wgt[p, g*9+k2] * x[b, y+i-1, x+j-1, ch]
//   oc = g*16+gc; f = g*144+gc*9+k2; k = f/256; ch = f%256; i=k/3; j=k%3
// Block = (b, y, 32-pixel half row). 512 threads.
// smem: xs[3][34][256] (haloed x tile) + wgts[32][144]  = 122880 bytes
// ---------------------------------------------------------------------------
__global__ __launch_bounds__(512) void invol_kernel(
    const float* __restrict__ x, float* __restrict__ out)
{
    extern __shared__ float sm3[];
    float* xs   = sm3;                       // [3][34][256]
    float* wgts = sm3 + 3 * 34 * 256;        // [32][144]

    const int x0 = blockIdx.x * 32;
    const int y  = blockIdx.y;
    const int b  = blockIdx.z;
    const int tid = threadIdx.x;

    // ---- load haloed x tile: rows y-1..y+1, cols x0-1..x0+32, all 256 ch ----
    float4* xs4 = (float4*)xs;
    for (int id = tid; id < 3 * 34 * 64; id += 512) {
        int r    = id / (34 * 64);
        int rem  = id - r * (34 * 64);
        int cidx = rem >> 6;
        int c4   = rem & 63;
        int gy = y - 1 + r;
        int gx = x0 - 1 + cidx;
        float4 v;
        if (gy >= 0 && gy < HH && gx >= 0 && gx < WW) {
            v = *(const float4*)(x + (((size_t)(b * HH + gy) * WW + gx) * CIN) + c4 * 4);
        } else {
            v = make_float4(0.f, 0.f, 0.f, 0.f);
        }
        xs4[(r * 34 + cidx) * 64 + c4] = v;
    }
    // ---- load wgt tile: 32 pixels x 144 (contiguous in global) ----
    {
        const size_t pbase = ((size_t)(b * HH + y) * WW + x0) * EOUT;
        float4* w4 = (float4*)wgts;
        const float4* g4 = (const float4*)(g_wgt + pbase);
        for (int id = tid; id < 32 * EOUT / 4; id += 512) w4[id] = g4[id];
    }
    __syncthreads();

    // ---- compute ----
    const int oc   = tid & 255;
    const int half = tid >> 8;          // 0 or 1
    const int g  = oc >> 4;
    const int gc = oc & 15;

    int off9[9];
    #pragma unroll
    for (int k2 = 0; k2 < 9; k2++) {
        int f  = g * 144 + gc * 9 + k2;
        int k  = f >> 8;
        int ch = f & 255;
        int i  = k / 3;
        int j  = k - i * 3;
        off9[k2] = (i * 34 + j) * 256 + ch;
    }

    const int wg9 = g * 9;
    float* outrow = out + ((size_t)(b * HH + y) * WW + x0) * CIN;

    #pragma unroll
    for (int it = 0; it < 16; it++) {
        int px = it * 2 + half;
        const float* wrow = wgts + px * EOUT + wg9;
        int xbase = px * 256;
        float acc = 0.f;
        #pragma unroll
        for (int k2 = 0; k2 < 9; k2++)
            acc += wrow[k2] * xs[off9[k2] + xbase];
        outrow[(size_t)px * CIN + oc] = acc;
    }
}

// ---------------------------------------------------------------------------
extern "C" void kernel_launch(void* const* d_in, const int* in_sizes, int n_in,
                              void* d_out, int out_size) {
    const float* x  = (const float*)d_in[0];
    const float* W1 = (const float*)d_in[1];
    const float* b1 = (const float*)d_in[2];
    const float* W2 = (const float*)d_in[3];
    const float* b2 = (const float*)d_in[4];
    float* out = (float*)d_out;

    static bool attr_done = false;
    if (!attr_done) {
        cudaFuncSetAttribute(gemm2_kernel,
            cudaFuncAttributeMaxDynamicSharedMemorySize, (64*65 + 64*EOUT) * 4);
        cudaFuncSetAttribute(invol_kernel,
            cudaFuncAttributeMaxDynamicSharedMemorySize, (3*34*256 + 32*EOUT) * 4);
        attr_done = true;
    }

    gemm1_kernel<<<PTOT / 128, 256>>>(x, W1, b1);
    gemm2_kernel<<<PTOT / 64, 256, (64*65 + 64*EOUT) * 4>>>(W2, b2);
    invol_kernel<<<dim3(WW / 32, HH, BATCH), 512, (3*34*256 + 32*EOUT) * 4>>>(x, out);
}

// round 3
// speedup vs baseline: 1.1080x; 1.1080x over previous
#include <cuda_runtime.h>
#include <cstdint>

#define BATCH 8
#define HH 64
#define WW 64
#define CIN 256
#define DMID 64
#define EOUT 144
#define PTOT (BATCH*HH*WW)   // 32768

// Scratch
__device__ float g_t[PTOT * DMID];     // 8.4 MB
__device__ float g_wgt[PTOT * EOUT];   // 18.9 MB

// packed fp32x2 FMA: d.lo += a.lo*b.lo ; d.hi += a.hi*b.hi (SASS FFMA2)
__device__ __forceinline__ void fma2(float2 &d, const float2 &a, const float2 &b) {
    asm("fma.rn.f32x2 %0, %1, %2, %3;"
        : "=l"(*reinterpret_cast<unsigned long long*>(&d))
        : "l"(*reinterpret_cast<const unsigned long long*>(&a)),
          "l"(*reinterpret_cast<const unsigned long long*>(&b)),
          "l"(*reinterpret_cast<unsigned long long*>(&d)));
}

// ---------------------------------------------------------------------------
// GEMM1: t[P,64] = x[P,256] @ W1[256,64] + b1
// K-packed f32x2. W1^T fully smem-resident [64][256]; A tiled [128][32] row-major.
// 256 threads: tm=tid>>4 (8 rows each), tn=tid&15 (4 cols each). Grid 256.
// ---------------------------------------------------------------------------
#define G1_AST 36      // A row stride (floats), 16B-multiple
#define G1_BST 258     // W1T row stride
#define G1_SMEM ((64*G1_BST + 128*G1_AST) * 4)

__global__ __launch_bounds__(256) void gemm1_kernel(
    const float* __restrict__ x, const float* __restrict__ W1,
    const float* __restrict__ b1)
{
    extern __shared__ float sm1[];
    float* Bs = sm1;                   // [64 n][G1_BST] : W1^T
    float* As = sm1 + 64 * G1_BST;     // [128 m][G1_AST]
    const int bm  = blockIdx.x * 128;
    const int tid = threadIdx.x;
    const int tm8 = (tid >> 4) * 8;
    const int tn4 = (tid & 15) * 4;

    // load W1^T : W1[k][n] -> Bs[n][k]
    #pragma unroll
    for (int p = 0; p < 16; p++) {
        int id = tid + p * 256;            // float4 id over W1
        int k  = id >> 4;
        int n4 = (id & 15) * 4;
        float4 v = ((const float4*)W1)[id];
        Bs[(n4+0)*G1_BST + k] = v.x;
        Bs[(n4+1)*G1_BST + k] = v.y;
        Bs[(n4+2)*G1_BST + k] = v.z;
        Bs[(n4+3)*G1_BST + k] = v.w;
    }

    float2 acc[8][4];
    #pragma unroll
    for (int i = 0; i < 8; i++)
        #pragma unroll
        for (int j = 0; j < 4; j++) acc[i][j] = make_float2(0.f, 0.f);

    for (int kt = 0; kt < 8; kt++) {
        __syncthreads();
        // load A tile 128 x 32, row-major, straight float4 copy
        #pragma unroll
        for (int p = 0; p < 4; p++) {
            int id = tid + p * 256;
            int r  = id >> 3;
            int c4 = (id & 7) * 4;
            float4 v = *(const float4*)(x + (size_t)(bm + r) * CIN + kt * 32 + c4);
            *(float4*)(As + r * G1_AST + c4) = v;
        }
        __syncthreads();

        #pragma unroll
        for (int kk = 0; kk < 32; kk += 2) {
            int k = kt * 32 + kk;
            float2 b[4], a[8];
            #pragma unroll
            for (int j = 0; j < 4; j++)
                b[j] = *(const float2*)(Bs + (tn4 + j) * G1_BST + k);
            #pragma unroll
            for (int i = 0; i < 8; i++)
                a[i] = *(const float2*)(As + (tm8 + i) * G1_AST + kk);
            #pragma unroll
            for (int i = 0; i < 8; i++)
                #pragma unroll
                for (int j = 0; j < 4; j++)
                    fma2(acc[i][j], a[i], b[j]);
        }
    }

    float4 bb = *(const float4*)(b1 + tn4);
    #pragma unroll
    for (int i = 0; i < 8; i++) {
        int row = bm + tm8 + i;
        float4 v = make_float4(acc[i][0].x + acc[i][0].y + bb.x,
                               acc[i][1].x + acc[i][1].y + bb.y,
                               acc[i][2].x + acc[i][2].y + bb.z,
                               acc[i][3].x + acc[i][3].y + bb.w);
        *(float4*)(g_t + (size_t)row * DMID + tn4) = v;
    }
}

// ---------------------------------------------------------------------------
// GEMM2: wgt[P,144] = t[P,64] @ W2[64,144] + b2
// K-packed f32x2, full K=64 resident. BM=64. 256 threads:
// tm=tid>>4 (4 rows each), tn=tid&15 (9 cols each). Grid 512.
// ---------------------------------------------------------------------------
#define G2_TST 68      // t-tile row stride (16B multiple)
#define G2_WST 66      // W2T row stride (even)
#define G2_SMEM ((EOUT*G2_WST + 64*G2_TST) * 4)

__global__ __launch_bounds__(256) void gemm2_kernel(
    const float* __restrict__ W2, const float* __restrict__ b2)
{
    extern __shared__ float sm2[];
    float* Ws = sm2;                   // [144 n][G2_WST] : W2^T
    float* Ts = sm2 + EOUT * G2_WST;   // [64 m][G2_TST]
    const int bm  = blockIdx.x * 64;
    const int tid = threadIdx.x;
    const int tm4 = (tid >> 4) * 4;
    const int tn9 = (tid & 15) * 9;

    // W2^T: W2[k][n] (64x144) -> Ws[n][k]
    #pragma unroll
    for (int p = 0; p < 36; p++) {
        int id = tid + p * 256;           // scalar id over 9216
        int k  = id / EOUT;
        int n  = id - k * EOUT;
        Ws[n * G2_WST + k] = W2[id];
    }
    // t tile 64x64, straight float4 copy
    #pragma unroll
    for (int p = 0; p < 4; p++) {
        int id = tid + p * 256;
        int r  = id >> 4;
        int c4 = (id & 15) * 4;
        float4 v = *(const float4*)(g_t + (size_t)(bm + r) * DMID + c4);
        *(float4*)(Ts + r * G2_TST + c4) = v;
    }
    __syncthreads();

    float2 acc[4][9];
    #pragma unroll
    for (int i = 0; i < 4; i++)
        #pragma unroll
        for (int j = 0; j < 9; j++) acc[i][j] = make_float2(0.f, 0.f);

    #pragma unroll 8
    for (int k = 0; k < 64; k += 2) {
        float2 a[4], b[9];
        #pragma unroll
        for (int i = 0; i < 4; i++)
            a[i] = *(const float2*)(Ts + (tm4 + i) * G2_TST + k);
        #pragma unroll
        for (int j = 0; j < 9; j++)
            b[j] = *(const float2*)(Ws + (tn9 + j) * G2_WST + k);
        #pragma unroll
        for (int i = 0; i < 4; i++)
            #pragma unroll
            for (int j = 0; j < 9; j++)
                fma2(acc[i][j], a[i], b[j]);
    }

    #pragma unroll
    for (int i = 0; i < 4; i++) {
        int row = bm + tm4 + i;
        float* dst = g_wgt + (size_t)row * EOUT + tn9;
        #pragma unroll
        for (int j = 0; j < 9; j++)
            dst[j] = acc[i][j].x + acc[i][j].y + b2[tn9 + j];
    }
}

// ---------------------------------------------------------------------------
// Involution. Block = 16-pixel strip, 256 threads (one oc each, 16 px loop).
// smem: xs[3][18][256] halo + wgts[16][144]  = 64.5KB -> 3 blocks/SM
// ---------------------------------------------------------------------------
#define IV_PX 16
#define IV_SMEM ((3*18*256 + IV_PX*EOUT) * 4)

__global__ __launch_bounds__(256) void invol_kernel(
    const float* __restrict__ x, float* __restrict__ out)
{
    extern __shared__ float sm3[];
    float* xs   = sm3;                       // [3][18][256]
    float* wgts = sm3 + 3 * 18 * 256;        // [16][144]

    const int x0 = blockIdx.x * IV_PX;
    const int y  = blockIdx.y;
    const int b  = blockIdx.z;
    const int tid = threadIdx.x;

    // halo x tile: rows y-1..y+1, cols x0-1..x0+16
    float4* xs4 = (float4*)xs;
    for (int id = tid; id < 3 * 18 * 64; id += 256) {
        int r    = id / (18 * 64);
        int rem  = id - r * (18 * 64);
        int cidx = rem >> 6;
        int c4   = rem & 63;
        int gy = y - 1 + r;
        int gx = x0 - 1 + cidx;
        float4 v = make_float4(0.f, 0.f, 0.f, 0.f);
        if (gy >= 0 && gy < HH && gx >= 0 && gx < WW)
            v = *(const float4*)(x + (((size_t)(b * HH + gy) * WW + gx) * CIN) + c4 * 4);
        xs4[(r * 18 + cidx) * 64 + c4] = v;
    }
    // wgt tile (contiguous)
    {
        const size_t pbase = ((size_t)(b * HH + y) * WW + x0) * EOUT;
        float4* w4 = (float4*)wgts;
        const float4* g4 = (const float4*)(g_wgt + pbase);
        #pragma unroll
        for (int p = 0; p < IV_PX * EOUT / 4 / 256 + 1; p++) {
            int id = tid + p * 256;
            if (id < IV_PX * EOUT / 4) w4[id] = g4[id];
        }
    }
    __syncthreads();

    const int oc = tid;
    const int g  = oc >> 4;
    const int gc = oc & 15;

    int off9[9];
    #pragma unroll
    for (int k2 = 0; k2 < 9; k2++) {
        int f  = g * 144 + gc * 9 + k2;
        int k  = f >> 8;
        int ch = f & 255;
        int i  = k / 3;
        int j  = k - i * 3;
        off9[k2] = (i * 18 + j) * 256 + ch;
    }

    const int wg9 = g * 9;
    float* outrow = out + ((size_t)(b * HH + y) * WW + x0) * CIN;

    #pragma unroll
    for (int px = 0; px < IV_PX; px++) {
        const float* wrow = wgts + px * EOUT + wg9;
        const float* xb   = xs + px * 256;
        float acc = 0.f;
        #pragma unroll
        for (int k2 = 0; k2 < 9; k2++)
            acc = fmaf(wrow[k2], xb[off9[k2]], acc);
        outrow[(size_t)px * CIN + oc] = acc;
    }
}

// ---------------------------------------------------------------------------
extern "C" void kernel_launch(void* const* d_in, const int* in_sizes, int n_in,
                              void* d_out, int out_size) {
    const float* x  = (const float*)d_in[0];
    const float* W1 = (const float*)d_in[1];
    const float* b1 = (const float*)d_in[2];
    const float* W2 = (const float*)d_in[3];
    const float* b2 = (const float*)d_in[4];
    float* out = (float*)d_out;

    static bool attr_done = false;
    if (!attr_done) {
        cudaFuncSetAttribute(gemm1_kernel,
            cudaFuncAttributeMaxDynamicSharedMemorySize, G1_SMEM);
        cudaFuncSetAttribute(gemm2_kernel,
            cudaFuncAttributeMaxDynamicSharedMemorySize, G2_SMEM);
        cudaFuncSetAttribute(invol_kernel,
            cudaFuncAttributeMaxDynamicSharedMemorySize, IV_SMEM);
        attr_done = true;
    }

    gemm1_kernel<<<PTOT / 128, 256, G1_SMEM>>>(x, W1, b1);
    gemm2_kernel<<<PTOT / 64, 256, G2_SMEM>>>(W2, b2);
    invol_kernel<<<dim3(WW / IV_PX, HH, BATCH), 256, IV_SMEM>>>(x, out);
}

// round 6
// speedup vs baseline: 1.1507x; 1.0385x over previous
#include <cuda_runtime.h>
#include <cstdint>

#define BATCH 8
#define HH 64
#define WW 64
#define CIN 256
#define DMID 64
#define EOUT 144
#define PTOT (BATCH*HH*WW)   // 32768

// Scratch
__device__ float g_t[PTOT * DMID];     // 8.4 MB
__device__ float g_wgt[PTOT * EOUT];   // 18.9 MB

// packed fp32x2 FMA: d.lo += a.lo*b.lo ; d.hi += a.hi*b.hi (SASS FFMA2)
__device__ __forceinline__ void fma2(float2 &d, const float2 &a, const float2 &b) {
    asm("fma.rn.f32x2 %0, %1, %2, %3;"
        : "=l"(*reinterpret_cast<unsigned long long*>(&d))
        : "l"(*reinterpret_cast<const unsigned long long*>(&a)),
          "l"(*reinterpret_cast<const unsigned long long*>(&b)),
          "l"(*reinterpret_cast<unsigned long long*>(&d)));
}

// ---------------------------------------------------------------------------
// GEMM1: t[P,64] = x[P,256] @ W1[256,64] + b1
// K-packed f32x2. W1^T fully smem-resident; A tiled [128][32] row-major.
// 256 threads, 2 CTAs/SM forced. Grid 256 -> single wave at 2/SM.
// ---------------------------------------------------------------------------
#define G1_AST 36      // A row stride (floats)
#define G1_BST 258     // W1T row stride
#define G1_SMEM ((64*G1_BST + 128*G1_AST) * 4)

__global__ __launch_bounds__(256, 2) void gemm1_kernel(
    const float* __restrict__ x, const float* __restrict__ W1,
    const float* __restrict__ b1)
{
    extern __shared__ float sm1[];
    float* Bs = sm1;                   // [64 n][G1_BST] : W1^T
    float* As = sm1 + 64 * G1_BST;     // [128 m][G1_AST]
    const int bm  = blockIdx.x * 128;
    const int tid = threadIdx.x;
    const int tm8 = (tid >> 4) * 8;
    const int tn4 = (tid & 15) * 4;

    // load W1^T : W1[k][n] -> Bs[n][k]
    #pragma unroll
    for (int p = 0; p < 16; p++) {
        int id = tid + p * 256;            // float4 id over W1
        int k  = id >> 4;
        int n4 = (id & 15) * 4;
        float4 v = ((const float4*)W1)[id];
        Bs[(n4+0)*G1_BST + k] = v.x;
        Bs[(n4+1)*G1_BST + k] = v.y;
        Bs[(n4+2)*G1_BST + k] = v.z;
        Bs[(n4+3)*G1_BST + k] = v.w;
    }

    float2 acc[8][4];
    #pragma unroll
    for (int i = 0; i < 8; i++)
        #pragma unroll
        for (int j = 0; j < 4; j++) acc[i][j] = make_float2(0.f, 0.f);

    for (int kt = 0; kt < 8; kt++) {
        __syncthreads();
        // load A tile 128 x 32, row-major, straight float4 copy
        #pragma unroll
        for (int p = 0; p < 4; p++) {
            int id = tid + p * 256;
            int r  = id >> 3;
            int c4 = (id & 7) * 4;
            float4 v = *(const float4*)(x + (size_t)(bm + r) * CIN + kt * 32 + c4);
            *(float4*)(As + r * G1_AST + c4) = v;
        }
        __syncthreads();

        #pragma unroll
        for (int kk = 0; kk < 32; kk += 2) {
            int k = kt * 32 + kk;
            float2 b[4], a[8];
            #pragma unroll
            for (int j = 0; j < 4; j++)
                b[j] = *(const float2*)(Bs + (tn4 + j) * G1_BST + k);
            #pragma unroll
            for (int i = 0; i < 8; i++)
                a[i] = *(const float2*)(As + (tm8 + i) * G1_AST + kk);
            #pragma unroll
            for (int i = 0; i < 8; i++)
                #pragma unroll
                for (int j = 0; j < 4; j++)
                    fma2(acc[i][j], a[i], b[j]);
        }
    }

    float4 bb = *(const float4*)(b1 + tn4);
    #pragma unroll
    for (int i = 0; i < 8; i++) {
        int row = bm + tm8 + i;
        float4 v = make_float4(acc[i][0].x + acc[i][0].y + bb.x,
                               acc[i][1].x + acc[i][1].y + bb.y,
                               acc[i][2].x + acc[i][2].y + bb.z,
                               acc[i][3].x + acc[i][3].y + bb.w);
        *(float4*)(g_t + (size_t)row * DMID + tn4) = v;
    }
}

// ---------------------------------------------------------------------------
// GEMM2: wgt[P,144] = t[P,64] @ W2[64,144] + b2
// K-packed f32x2, full K=64 resident. BM=64, 2 CTAs/SM forced. Grid 512.
// ---------------------------------------------------------------------------
#define G2_TST 68
#define G2_WST 66
#define G2_SMEM ((EOUT*G2_WST + 64*G2_TST) * 4)

__global__ __launch_bounds__(256, 2) void gemm2_kernel(
    const float* __restrict__ W2, const float* __restrict__ b2)
{
    extern __shared__ float sm2[];
    float* Ws = sm2;                   // [144 n][G2_WST] : W2^T
    float* Ts = sm2 + EOUT * G2_WST;   // [64 m][G2_TST]
    const int bm  = blockIdx.x * 64;
    const int tid = threadIdx.x;
    const int tm4 = (tid >> 4) * 4;
    const int tn9 = (tid & 15) * 9;

    // W2^T via float4 loads: W2 is [64][144] = 2304 float4
    #pragma unroll
    for (int p = 0; p < 9; p++) {
        int id = tid + p * 256;           // float4 id
        int k  = id / 36;
        int n4 = (id - k * 36) * 4;
        float4 v = ((const float4*)W2)[id];
        Ws[(n4+0) * G2_WST + k] = v.x;
        Ws[(n4+1) * G2_WST + k] = v.y;
        Ws[(n4+2) * G2_WST + k] = v.z;
        Ws[(n4+3) * G2_WST + k] = v.w;
    }
    // t tile 64x64, straight float4 copy
    #pragma unroll
    for (int p = 0; p < 4; p++) {
        int id = tid + p * 256;
        int r  = id >> 4;
        int c4 = (id & 15) * 4;
        float4 v = *(const float4*)(g_t + (size_t)(bm + r) * DMID + c4);
        *(float4*)(Ts + r * G2_TST + c4) = v;
    }
    __syncthreads();

    float2 acc[4][9];
    #pragma unroll
    for (int i = 0; i < 4; i++)
        #pragma unroll
        for (int j = 0; j < 9; j++) acc[i][j] = make_float2(0.f, 0.f);

    #pragma unroll 8
    for (int k = 0; k < 64; k += 2) {
        float2 a[4], b[9];
        #pragma unroll
        for (int i = 0; i < 4; i++)
            a[i] = *(const float2*)(Ts + (tm4 + i) * G2_TST + k);
        #pragma unroll
        for (int j = 0; j < 9; j++)
            b[j] = *(const float2*)(Ws + (tn9 + j) * G2_WST + k);
        #pragma unroll
        for (int i = 0; i < 4; i++)
            #pragma unroll
            for (int j = 0; j < 9; j++)
                fma2(acc[i][j], a[i], b[j]);
    }

    #pragma unroll
    for (int i = 0; i < 4; i++) {
        int row = bm + tm4 + i;
        float* dst = g_wgt + (size_t)row * EOUT + tn9;
        #pragma unroll
        for (int j = 0; j < 9; j++)
            dst[j] = acc[i][j].x + acc[i][j].y + b2[tn9 + j];
    }
}

// ---------------------------------------------------------------------------
// Involution. Block = 16-pixel strip, 256 threads (one oc each, 16 px loop).
// smem: xs[3][18][256] halo + wgts[16][144]  = 64.5KB -> 3 blocks/SM
// ---------------------------------------------------------------------------
#define IV_PX 16
#define IV_SMEM ((3*18*256 + IV_PX*EOUT) * 4)

__global__ __launch_bounds__(256) void invol_kernel(
    const float* __restrict__ x, float* __restrict__ out)
{
    extern __shared__ float sm3[];
    float* xs   = sm3;                       // [3][18][256]
    float* wgts = sm3 + 3 * 18 * 256;        // [16][144]

    const int x0 = blockIdx.x * IV_PX;
    const int y  = blockIdx.y;
    const int b  = blockIdx.z;
    const int tid = threadIdx.x;

    // halo x tile: rows y-1..y+1, cols x0-1..x0+16
    float4* xs4 = (float4*)xs;
    for (int id = tid; id < 3 * 18 * 64; id += 256) {
        int r    = id / (18 * 64);
        int rem  = id - r * (18 * 64);
        int cidx = rem >> 6;
        int c4   = rem & 63;
        int gy = y - 1 + r;
        int gx = x0 - 1 + cidx;
        float4 v = make_float4(0.f, 0.f, 0.f, 0.f);
        if (gy >= 0 && gy < HH && gx >= 0 && gx < WW)
            v = *(const float4*)(x + (((size_t)(b * HH + gy) * WW + gx) * CIN) + c4 * 4);
        xs4[(r * 18 + cidx) * 64 + c4] = v;
    }
    // wgt tile (contiguous)
    {
        const size_t pbase = ((size_t)(b * HH + y) * WW + x0) * EOUT;
        float4* w4 = (float4*)wgts;
        const float4* g4 = (const float4*)(g_wgt + pbase);
        #pragma unroll
        for (int p = 0; p < IV_PX * EOUT / 4 / 256 + 1; p++) {
            int id = tid + p * 256;
            if (id < IV_PX * EOUT / 4) w4[id] = g4[id];
        }
    }
    __syncthreads();

    const int oc = tid;
    const int g  = oc >> 4;
    const int gc = oc & 15;

    int off9[9];
    #pragma unroll
    for (int k2 = 0; k2 < 9; k2++) {
        int f  = g * 144 + gc * 9 + k2;
        int k  = f >> 8;
        int ch = f & 255;
        int i  = k / 3;
        int j  = k - i * 3;
        off9[k2] = (i * 18 + j) * 256 + ch;
    }

    const int wg9 = g * 9;
    float* outrow = out + ((size_t)(b * HH + y) * WW + x0) * CIN;

    #pragma unroll
    for (int px = 0; px < IV_PX; px++) {
        const float* wrow = wgts + px * EOUT + wg9;
        const float* xb   = xs + px * 256;
        float acc = 0.f;
        #pragma unroll
        for (int k2 = 0; k2 < 9; k2++)
            acc = fmaf(wrow[k2], xb[off9[k2]], acc);
        outrow[(size_t)px * CIN + oc] = acc;
    }
}

// ---------------------------------------------------------------------------
extern "C" void kernel_launch(void* const* d_in, const int* in_sizes, int n_in,
                              void* d_out, int out_size) {
    const float* x  = (const float*)d_in[0];
    const float* W1 = (const float*)d_in[1];
    const float* b1 = (const float*)d_in[2];
    const float* W2 = (const float*)d_in[3];
    const float* b2 = (const float*)d_in[4];
    float* out = (float*)d_out;

    static bool attr_done = false;
    if (!attr_done) {
        cudaFuncSetAttribute(gemm1_kernel,
            cudaFuncAttributeMaxDynamicSharedMemorySize, G1_SMEM);
        cudaFuncSetAttribute(gemm2_kernel,
            cudaFuncAttributeMaxDynamicSharedMemorySize, G2_SMEM);
        cudaFuncSetAttribute(invol_kernel,
            cudaFuncAttributeMaxDynamicSharedMemorySize, IV_SMEM);
        attr_done = true;
    }

    gemm1_kernel<<<PTOT / 128, 256, G1_SMEM>>>(x, W1, b1);
    gemm2_kernel<<<PTOT / 64, 256, G2_SMEM>>>(W2, b2);
    invol_kernel<<<dim3(WW / IV_PX, HH, BATCH), 256, IV_SMEM>>>(x, out);
}